// round 7
// baseline (speedup 1.0000x reference)
#include <cuda_runtime.h>
#include <math.h>

// Problem constants (match reference)
#define Hc 384
#define Wc 384
#define Bc 4
#define Mc 192
#define EPSc 1e-6f
#define MAXD 543.0580079f        // sqrt(384^2 + 384^2)
#define Cc (EPSc / MAXD)         // EPS / MAX_DIST

// Tiling: 4 resident blocks per SM for latency hiding
#define TPB 128
#define JT 3          // columns per thread: 128*3 = 384 = W
#define RR 3          // rows per block
#define MC 8          // m-chunk (4 packed pairs)
#define TILES (Hc / RR)            // 128 row tiles per image
#define NBLOCKS (Bc * TILES)       // 512 blocks

// Persistent scratch. Zero-init is semantically "+inf" for t2 keys
// (key = 0x7F800000 - bits, atomicMax), 0 for the counter.
// Finisher block resets both -> deterministic graph replays.
__device__ int   g_t2key[Bc * Mc];
__device__ float g_t1part[NBLOCKS];
__device__ float g_ppart[NBLOCKS];
__device__ int   g_ctr;

// ---- Blackwell packed fp32x2 helpers ----
__device__ __forceinline__ float2 f2add(float2 a, float2 b) {
    unsigned long long ua = *reinterpret_cast<unsigned long long*>(&a);
    unsigned long long ub = *reinterpret_cast<unsigned long long*>(&b);
    unsigned long long ur;
    asm("add.rn.f32x2 %0, %1, %2;" : "=l"(ur) : "l"(ua), "l"(ub));
    return *reinterpret_cast<float2*>(&ur);
}
__device__ __forceinline__ float2 f2sub(float2 a, float2 b) {
    unsigned long long ua = *reinterpret_cast<unsigned long long*>(&a);
    unsigned long long ub = *reinterpret_cast<unsigned long long*>(&b);
    unsigned long long ur;
    asm("sub.rn.f32x2 %0, %1, %2;" : "=l"(ur) : "l"(ua), "l"(ub));
    return *reinterpret_cast<float2*>(&ur);
}
__device__ __forceinline__ float2 f2mul(float2 a, float2 b) {
    unsigned long long ua = *reinterpret_cast<unsigned long long*>(&a);
    unsigned long long ub = *reinterpret_cast<unsigned long long*>(&b);
    unsigned long long ur;
    asm("mul.rn.f32x2 %0, %1, %2;" : "=l"(ur) : "l"(ua), "l"(ub));
    return *reinterpret_cast<float2*>(&ur);
}

__global__ __launch_bounds__(TPB, 4) void whd_kernel(
    const float* __restrict__ prob,
    const float* __restrict__ gt,
    const float* __restrict__ osz,
    float* __restrict__ out)
{
    const int blk  = blockIdx.x;
    const int b    = blk / TILES;
    const int row0 = (blk % TILES) * RR;
    const int tid  = threadIdx.x;
    const int lane = tid & 31;
    const int wrp  = tid >> 5;

    __shared__ __align__(16) float s_gx[Mc];
    __shared__ __align__(16) float s_dy2[RR * Mc];
    __shared__ __align__(16) int s_t2min[Mc * 32];   // [m][lane], float bits
    __shared__ float s_red[8];
    __shared__ int s_last;

    // init block-local t2 table to +inf (12 ST.128 per thread)
    {
        int4 inf4 = make_int4(0x7F800000, 0x7F800000, 0x7F800000, 0x7F800000);
        int4* p4 = (int4*)s_t2min;
#pragma unroll
        for (int k = 0; k < (Mc * 32 / 4) / TPB; k++)
            p4[tid + k * TPB] = inf4;
    }

    const float fy = osz[b * 2 + 0] * (1.0f / (float)Hc);
    const float fx = osz[b * 2 + 1] * (1.0f / (float)Wc);

    // gt prologue: normalized coords, per-row dy^2
    {
        const float2* gt2 = (const float2*)gt;
        for (int m = tid; m < Mc; m += TPB) {
            float2 g = gt2[b * Mc + m];
            float gy = g.x * fy;
            s_gx[m] = g.y * fx;
#pragma unroll
            for (int k = 0; k < RR; k++) {
                float dy = (float)(row0 + k) * fy - gy;
                s_dy2[k * Mc + m] = dy * dy;
            }
        }
    }

    // Per-pixel p and 1/w^2 (w = p^4 + EPS/MAX_DIST), duplicated for f32x2
    const float* pimg = prob + b * Hc * Wc;
    float  pr[RR][JT];
    float2 iw2d[RR][JT];
    float2 xjd[JT];
#pragma unroll
    for (int jt = 0; jt < JT; jt++) {
        float xv = (float)(tid + jt * TPB) * fx;
        xjd[jt] = make_float2(xv, xv);
    }
#pragma unroll
    for (int i = 0; i < RR; i++) {
#pragma unroll
        for (int jt = 0; jt < JT; jt++) {
            float p = pimg[(row0 + i) * Wc + tid + jt * TPB];
            pr[i][jt] = p;
            float p2 = p * p;
            float w  = p2 * p2 + Cc;
            float iw = __fdividef(1.0f, w);
            float iw2 = iw * iw;
            iw2d[i][jt] = make_float2(iw2, iw2);
        }
    }
    __syncthreads();

    float pixmin[RR][JT];
#pragma unroll
    for (int i = 0; i < RR; i++)
#pragma unroll
        for (int jt = 0; jt < JT; jt++) pixmin[i][jt] = 3.0e38f;

    const float2* s_gx2 = (const float2*)s_gx;

    for (int m0 = 0; m0 < Mc; m0 += MC) {
        float2 dx2p[JT][MC / 2];
        float2 t2p[MC / 2];
#pragma unroll
        for (int mp = 0; mp < MC / 2; mp++) {
            float2 gxp = s_gx2[(m0 >> 1) + mp];          // broadcast LDS.64
            t2p[mp] = make_float2(3.0e38f, 3.0e38f);
#pragma unroll
            for (int jt = 0; jt < JT; jt++) {
                float2 dxp = f2sub(xjd[jt], gxp);
                dx2p[jt][mp] = f2mul(dxp, dxp);
            }
        }
#pragma unroll
        for (int i = 0; i < RR; i++) {
            const float2* dy2row = (const float2*)(s_dy2 + i * Mc + m0);
#pragma unroll
            for (int mp = 0; mp < MC / 2; mp++) {
                float2 dy2p = dy2row[mp];                 // broadcast LDS.64
#pragma unroll
                for (int jt = 0; jt < JT; jt++) {
                    float2 d2 = f2add(dy2p, dx2p[jt][mp]);
                    float2 t  = f2mul(d2, iw2d[i][jt]);
                    pixmin[i][jt] = fminf(pixmin[i][jt], fminf(d2.x, d2.y));
                    t2p[mp].x = fminf(t2p[mp].x, t.x);
                    t2p[mp].y = fminf(t2p[mp].y, t.y);
                }
            }
        }
        // per-lane mins -> block t2 table (spread-bank ATOMS, no result dep)
#pragma unroll
        for (int mp = 0; mp < MC / 2; mp++) {
            atomicMin(&s_t2min[(m0 + 2 * mp)     * 32 + lane],
                      __float_as_int(t2p[mp].x));
            atomicMin(&s_t2min[(m0 + 2 * mp + 1) * 32 + lane],
                      __float_as_int(t2p[mp].y));
        }
    }

    // term1 partials: sum p * sqrt(min_m d2), and sum p
    float t1p = 0.0f, pp = 0.0f;
#pragma unroll
    for (int i = 0; i < RR; i++) {
#pragma unroll
        for (int jt = 0; jt < JT; jt++) {
            t1p += pr[i][jt] * sqrtf(pixmin[i][jt]);
            pp  += pr[i][jt];
        }
    }
#pragma unroll
    for (int off = 16; off >= 1; off >>= 1) {
        t1p += __shfl_xor_sync(0xffffffffu, t1p, off);
        pp  += __shfl_xor_sync(0xffffffffu, pp,  off);
    }
    if (lane == 0) { s_red[wrp] = t1p; s_red[4 + wrp] = pp; }
    __syncthreads();   // also covers s_t2min writes
    if (tid == 0) {
        g_t1part[blk] = s_red[0] + s_red[1] + s_red[2] + s_red[3];
        g_ppart[blk]  = s_red[4] + s_red[5] + s_red[6] + s_red[7];
    }

    // block t2 table -> global keys (m = tid, m = 128 + tid if < 192)
    {
        for (int m = tid; m < Mc; m += TPB) {
            const int4* row = (const int4*)&s_t2min[m * 32];
            int4 a = row[0], c = row[1], d = row[2], e = row[3];
            int v0 = min(min(a.x, a.y), min(a.z, a.w));
            int v1 = min(min(c.x, c.y), min(c.z, c.w));
            int v2 = min(min(d.x, d.y), min(d.z, d.w));
            int v3 = min(min(e.x, e.y), min(e.z, e.w));
            int4 f = row[4], g = row[5], h2 = row[6], k2 = row[7];
            int v4 = min(min(f.x, f.y), min(f.z, f.w));
            int v5 = min(min(g.x, g.y), min(g.z, g.w));
            int v6 = min(min(h2.x, h2.y), min(h2.z, h2.w));
            int v7 = min(min(k2.x, k2.y), min(k2.z, k2.w));
            int v = min(min(min(v0, v1), min(v2, v3)),
                        min(min(v4, v5), min(v6, v7)));
            atomicMax(&g_t2key[b * Mc + m], 0x7F800000 - v);
        }
    }

    // ---- last-block finalize ----
    __threadfence();
    __syncthreads();
    if (tid == 0) s_last = (atomicAdd(&g_ctr, 1) == NBLOCKS - 1);
    __syncthreads();
    if (!s_last) return;

    __shared__ float s_t2[Bc], s_t1s[Bc], s_pps[Bc];
    // term2: 768 keys over 128 threads, 6 each; image = tid/32 = wrp
    {
        float acc = 0.0f;
#pragma unroll
        for (int k = 0; k < 6; k++) {
            int idx = tid * 6 + k;
            int key = __ldcg(&g_t2key[idx]);
            float v = __int_as_float(0x7F800000 - key);
            acc += fminf(sqrtf(v), MAXD);
            g_t2key[idx] = 0;                    // reset for next call
        }
#pragma unroll
        for (int off = 16; off >= 1; off >>= 1)
            acc += __shfl_xor_sync(0xffffffffu, acc, off);
        if (lane == 0) s_t2[wrp] = acc;          // warp w == image w
    }
    // term1: warp w reduces the 128 block-partials of image w (4 per lane)
    {
        if (wrp < Bc) {
            float t1 = 0.0f, ps = 0.0f;
#pragma unroll
            for (int k = 0; k < TILES / 32; k++) {
                t1 += __ldcg(&g_t1part[wrp * TILES + k * 32 + lane]);
                ps += __ldcg(&g_ppart [wrp * TILES + k * 32 + lane]);
            }
#pragma unroll
            for (int off = 16; off >= 1; off >>= 1) {
                t1 += __shfl_xor_sync(0xffffffffu, t1, off);
                ps += __shfl_xor_sync(0xffffffffu, ps, off);
            }
            if (lane == 0) { s_t1s[wrp] = t1; s_pps[wrp] = ps; }
        }
    }
    __syncthreads();
    if (tid == 0) {
        float res = 0.0f;
#pragma unroll
        for (int b2 = 0; b2 < Bc; b2++) {
            res += s_t1s[b2] / (s_pps[b2] + EPSc);
            res += s_t2[b2] * (1.0f / (float)Mc);
        }
        out[0] = res * (1.0f / (float)Bc);
        g_ctr = 0;                               // reset for next call
    }
}

extern "C" void kernel_launch(void* const* d_in, const int* in_sizes, int n_in,
                              void* d_out, int out_size) {
    const float* prob = (const float*)d_in[0];
    const float* gt   = (const float*)d_in[1];
    const float* osz  = (const float*)d_in[2];
    float* out = (float*)d_out;

    whd_kernel<<<NBLOCKS, TPB>>>(prob, gt, osz, out);
}

// round 8
// speedup vs baseline: 1.0667x; 1.0667x over previous
#include <cuda_runtime.h>
#include <math.h>

// Problem constants (match reference)
#define Hc 384
#define Wc 384
#define Bc 4
#define Mc 192
#define EPSc 1e-6f
#define MAXD 543.0580079f        // sqrt(384^2 + 384^2)
#define Cc (EPSc / MAXD)         // EPS / MAX_DIST

// Tiling (R6-proven shape: 256 blocks, 2/SM)
#define TPB 128
#define JT 3          // columns per thread: 128*3 = 384 = W
#define RR 6          // rows per block
#define MC 8          // m-chunk (4 packed pairs)
#define TILES (Hc / RR)            // 64 row tiles per image
#define NBLOCKS (Bc * TILES)       // 256 blocks

// Persistent scratch. Zero-init is semantically "+inf" for t2 keys
// (key = 0x7F800000 - bits, atomicMax), 0 for the counter.
// Finisher block resets both -> deterministic graph replays.
__device__ int   g_t2key[Bc * Mc];
__device__ float g_t1part[NBLOCKS];
__device__ float g_ppart[NBLOCKS];
__device__ int   g_ctr;

// ---- Blackwell packed fp32x2 helpers ----
__device__ __forceinline__ float2 f2add(float2 a, float2 b) {
    unsigned long long ua = *reinterpret_cast<unsigned long long*>(&a);
    unsigned long long ub = *reinterpret_cast<unsigned long long*>(&b);
    unsigned long long ur;
    asm("add.rn.f32x2 %0, %1, %2;" : "=l"(ur) : "l"(ua), "l"(ub));
    return *reinterpret_cast<float2*>(&ur);
}
__device__ __forceinline__ float2 f2sub(float2 a, float2 b) {
    unsigned long long ua = *reinterpret_cast<unsigned long long*>(&a);
    unsigned long long ub = *reinterpret_cast<unsigned long long*>(&b);
    unsigned long long ur;
    asm("sub.rn.f32x2 %0, %1, %2;" : "=l"(ur) : "l"(ua), "l"(ub));
    return *reinterpret_cast<float2*>(&ur);
}
__device__ __forceinline__ float2 f2mul(float2 a, float2 b) {
    unsigned long long ua = *reinterpret_cast<unsigned long long*>(&a);
    unsigned long long ub = *reinterpret_cast<unsigned long long*>(&b);
    unsigned long long ur;
    asm("mul.rn.f32x2 %0, %1, %2;" : "=l"(ur) : "l"(ua), "l"(ub));
    return *reinterpret_cast<float2*>(&ur);
}

__global__ __launch_bounds__(TPB) void whd_kernel(
    const float* __restrict__ prob,
    const float* __restrict__ gt,
    const float* __restrict__ osz,
    float* __restrict__ out)
{
    const int blk  = blockIdx.x;
    const int b    = blk / TILES;
    const int row0 = (blk % TILES) * RR;
    const int tid  = threadIdx.x;
    const int lane = tid & 31;
    const int wrp  = tid >> 5;

    __shared__ __align__(16) float s_gx[Mc];
    __shared__ __align__(16) float s_dy2[RR * Mc];
    __shared__ __align__(16) int s_t2min[Mc];    // one slot per m, float bits
    __shared__ float s_red[8];
    __shared__ int s_last;

    // init t2 table to +inf (192 entries, 2 loops of 96... use strided)
    for (int m = tid; m < Mc; m += TPB) s_t2min[m] = 0x7F800000;

    const float fy = osz[b * 2 + 0] * (1.0f / (float)Hc);
    const float fx = osz[b * 2 + 1] * (1.0f / (float)Wc);

    // gt prologue: normalized coords, per-row dy^2
    {
        const float2* gt2 = (const float2*)gt;
        for (int m = tid; m < Mc; m += TPB) {
            float2 g = gt2[b * Mc + m];
            float gy = g.x * fy;
            s_gx[m] = g.y * fx;
#pragma unroll
            for (int k = 0; k < RR; k++) {
                float dy = (float)(row0 + k) * fy - gy;
                s_dy2[k * Mc + m] = dy * dy;
            }
        }
    }

    // Per-pixel p and 1/w^2 (w = p^4 + EPS/MAX_DIST), duplicated for f32x2
    const float* pimg = prob + b * Hc * Wc;
    float  pr[RR][JT];
    float2 iw2d[RR][JT];
    float2 xjd[JT];
#pragma unroll
    for (int jt = 0; jt < JT; jt++) {
        float xv = (float)(tid + jt * TPB) * fx;
        xjd[jt] = make_float2(xv, xv);
    }
#pragma unroll
    for (int i = 0; i < RR; i++) {
#pragma unroll
        for (int jt = 0; jt < JT; jt++) {
            float p = pimg[(row0 + i) * Wc + tid + jt * TPB];
            pr[i][jt] = p;
            float p2 = p * p;
            float w  = p2 * p2 + Cc;
            float iw = __fdividef(1.0f, w);
            float iw2 = iw * iw;
            iw2d[i][jt] = make_float2(iw2, iw2);
        }
    }
    __syncthreads();

    float pixmin[RR][JT];
#pragma unroll
    for (int i = 0; i < RR; i++)
#pragma unroll
        for (int jt = 0; jt < JT; jt++) pixmin[i][jt] = 3.0e38f;

    const float2* s_gx2 = (const float2*)s_gx;

#pragma unroll 2
    for (int m0 = 0; m0 < Mc; m0 += MC) {
        float2 dx2p[JT][MC / 2];
        float2 t2p[MC / 2];
#pragma unroll
        for (int mp = 0; mp < MC / 2; mp++) {
            float2 gxp = s_gx2[(m0 >> 1) + mp];          // broadcast LDS.64
            t2p[mp] = make_float2(3.0e38f, 3.0e38f);
#pragma unroll
            for (int jt = 0; jt < JT; jt++) {
                float2 dxp = f2sub(xjd[jt], gxp);
                dx2p[jt][mp] = f2mul(dxp, dxp);
            }
        }
#pragma unroll
        for (int i = 0; i < RR; i++) {
            const float2* dy2row = (const float2*)(s_dy2 + i * Mc + m0);
#pragma unroll
            for (int mp = 0; mp < MC / 2; mp++) {
                float2 dy2p = dy2row[mp];                 // broadcast LDS.64
#pragma unroll
                for (int jt = 0; jt < JT; jt++) {
                    float2 d2 = f2add(dy2p, dx2p[jt][mp]);
                    float2 t  = f2mul(d2, iw2d[i][jt]);
                    pixmin[i][jt] = fminf(pixmin[i][jt], fminf(d2.x, d2.y));
                    t2p[mp].x = fminf(t2p[mp].x, t.x);
                    t2p[mp].y = fminf(t2p[mp].y, t.y);
                }
            }
        }
        // per-thread mins -> single slot per m (32 cyc/warp single-bank ATOMS)
#pragma unroll
        for (int mp = 0; mp < MC / 2; mp++) {
            atomicMin(&s_t2min[m0 + 2 * mp],     __float_as_int(t2p[mp].x));
            atomicMin(&s_t2min[m0 + 2 * mp + 1], __float_as_int(t2p[mp].y));
        }
    }

    // term1 partials: sum p * sqrt(min_m d2), and sum p
    float t1p = 0.0f, pp = 0.0f;
#pragma unroll
    for (int i = 0; i < RR; i++) {
#pragma unroll
        for (int jt = 0; jt < JT; jt++) {
            t1p += pr[i][jt] * sqrtf(pixmin[i][jt]);
            pp  += pr[i][jt];
        }
    }
#pragma unroll
    for (int off = 16; off >= 1; off >>= 1) {
        t1p += __shfl_xor_sync(0xffffffffu, t1p, off);
        pp  += __shfl_xor_sync(0xffffffffu, pp,  off);
    }
    if (lane == 0) { s_red[wrp] = t1p; s_red[4 + wrp] = pp; }
    __syncthreads();   // also covers s_t2min atomics
    if (tid == 0) {
        g_t1part[blk] = s_red[0] + s_red[1] + s_red[2] + s_red[3];
        g_ppart[blk]  = s_red[4] + s_red[5] + s_red[6] + s_red[7];
    }

    // block t2 mins -> global keys (m = tid, m = 128 + tid if < 192)
    for (int m = tid; m < Mc; m += TPB)
        atomicMax(&g_t2key[b * Mc + m], 0x7F800000 - s_t2min[m]);

    // ---- last-block finalize ----
    __threadfence();
    __syncthreads();
    if (tid == 0) s_last = (atomicAdd(&g_ctr, 1) == NBLOCKS - 1);
    __syncthreads();
    if (!s_last) return;

    __shared__ float s_t2[Bc], s_t1s[Bc], s_pps[Bc];
    // term2: 768 keys over 128 threads, 6 each; image = tid/32 = wrp
    {
        float acc = 0.0f;
#pragma unroll
        for (int k = 0; k < 6; k++) {
            int idx = tid * 6 + k;
            int key = __ldcg(&g_t2key[idx]);
            float v = __int_as_float(0x7F800000 - key);
            acc += fminf(sqrtf(v), MAXD);
            g_t2key[idx] = 0;                    // reset for next call
        }
#pragma unroll
        for (int off = 16; off >= 1; off >>= 1)
            acc += __shfl_xor_sync(0xffffffffu, acc, off);
        if (lane == 0) s_t2[wrp] = acc;          // warp w == image w
    }
    // term1: warp w reduces the 64 block-partials of image w (2 per lane)
    {
        if (wrp < Bc) {
            float t1 = __ldcg(&g_t1part[wrp * TILES + lane]) +
                       __ldcg(&g_t1part[wrp * TILES + 32 + lane]);
            float ps = __ldcg(&g_ppart [wrp * TILES + lane]) +
                       __ldcg(&g_ppart [wrp * TILES + 32 + lane]);
#pragma unroll
            for (int off = 16; off >= 1; off >>= 1) {
                t1 += __shfl_xor_sync(0xffffffffu, t1, off);
                ps += __shfl_xor_sync(0xffffffffu, ps, off);
            }
            if (lane == 0) { s_t1s[wrp] = t1; s_pps[wrp] = ps; }
        }
    }
    __syncthreads();
    if (tid == 0) {
        float res = 0.0f;
#pragma unroll
        for (int b2 = 0; b2 < Bc; b2++) {
            res += s_t1s[b2] / (s_pps[b2] + EPSc);
            res += s_t2[b2] * (1.0f / (float)Mc);
        }
        out[0] = res * (1.0f / (float)Bc);
        g_ctr = 0;                               // reset for next call
    }
}

extern "C" void kernel_launch(void* const* d_in, const int* in_sizes, int n_in,
                              void* d_out, int out_size) {
    const float* prob = (const float*)d_in[0];
    const float* gt   = (const float*)d_in[1];
    const float* osz  = (const float*)d_in[2];
    float* out = (float*)d_out;

    whd_kernel<<<NBLOCKS, TPB>>>(prob, gt, osz, out);
}

// round 10
// speedup vs baseline: 1.0808x; 1.0133x over previous
#include <cuda_runtime.h>
#include <math.h>

// Problem constants (match reference)
#define Hc 384
#define Wc 384
#define Bc 4
#define Mc 192
#define EPSc 1e-6f
#define MAXD 543.0580079f        // sqrt(384^2 + 384^2)
#define Cc (EPSc / MAXD)         // EPS / MAX_DIST

// Tiling: 256 blocks (2/SM), 6 warps/block -> 3 warps/SMSP on critical SMs
#define TPB 192
#define JT 2          // columns per thread: 192*2 = 384 = W
#define RR 6          // rows per block
#define MC 8          // m-chunk (4 packed pairs)
#define TILES (Hc / RR)            // 64 row tiles per image
#define NBLOCKS (Bc * TILES)       // 256 blocks

// Persistent scratch. Zero-init is semantically "+inf" for t2 keys
// (key = 0x7F800000 - bits, atomicMax), 0 for the counter.
// Finisher block resets both -> deterministic graph replays.
__device__ int   g_t2key[Bc * Mc];
__device__ float g_t1part[NBLOCKS];
__device__ float g_ppart[NBLOCKS];
__device__ int   g_ctr;

// ---- Blackwell packed fp32x2 helpers ----
__device__ __forceinline__ float2 f2add(float2 a, float2 b) {
    unsigned long long ua = *reinterpret_cast<unsigned long long*>(&a);
    unsigned long long ub = *reinterpret_cast<unsigned long long*>(&b);
    unsigned long long ur;
    asm("add.rn.f32x2 %0, %1, %2;" : "=l"(ur) : "l"(ua), "l"(ub));
    return *reinterpret_cast<float2*>(&ur);
}
__device__ __forceinline__ float2 f2sub(float2 a, float2 b) {
    unsigned long long ua = *reinterpret_cast<unsigned long long*>(&a);
    unsigned long long ub = *reinterpret_cast<unsigned long long*>(&b);
    unsigned long long ur;
    asm("sub.rn.f32x2 %0, %1, %2;" : "=l"(ur) : "l"(ua), "l"(ub));
    return *reinterpret_cast<float2*>(&ur);
}
__device__ __forceinline__ float2 f2mul(float2 a, float2 b) {
    unsigned long long ua = *reinterpret_cast<unsigned long long*>(&a);
    unsigned long long ub = *reinterpret_cast<unsigned long long*>(&b);
    unsigned long long ur;
    asm("mul.rn.f32x2 %0, %1, %2;" : "=l"(ur) : "l"(ua), "l"(ub));
    return *reinterpret_cast<float2*>(&ur);
}

__global__ __launch_bounds__(TPB) void whd_kernel(
    const float* __restrict__ prob,
    const float* __restrict__ gt,
    const float* __restrict__ osz,
    float* __restrict__ out)
{
    const int blk  = blockIdx.x;
    const int b    = blk / TILES;
    const int row0 = (blk % TILES) * RR;
    const int tid  = threadIdx.x;
    const int lane = tid & 31;
    const int wrp  = tid >> 5;

    __shared__ __align__(16) float s_gx[Mc];
    __shared__ __align__(16) float s_dy2[RR * Mc];
    __shared__ __align__(16) int s_t2min[Mc];    // one slot per m, float bits
    __shared__ float s_red[12];
    __shared__ int s_last;

    // init t2 table to +inf (192 entries, 1 per thread)
    s_t2min[tid] = 0x7F800000;

    const float fy = osz[b * 2 + 0] * (1.0f / (float)Hc);
    const float fx = osz[b * 2 + 1] * (1.0f / (float)Wc);

    // gt prologue: normalized coords, per-row dy^2 (1 m per thread)
    {
        const float2* gt2 = (const float2*)gt;
        float2 g = gt2[b * Mc + tid];
        float gy = g.x * fy;
        s_gx[tid] = g.y * fx;
#pragma unroll
        for (int k = 0; k < RR; k++) {
            float dy = (float)(row0 + k) * fy - gy;
            s_dy2[k * Mc + tid] = dy * dy;
        }
    }

    // Per-pixel p and 1/w^2 (w = p^4 + EPS/MAX_DIST), duplicated for f32x2
    const float* pimg = prob + b * Hc * Wc;
    float  pr[RR][JT];
    float2 iw2d[RR][JT];
    float2 xjd[JT];
#pragma unroll
    for (int jt = 0; jt < JT; jt++) {
        float xv = (float)(tid + jt * TPB) * fx;
        xjd[jt] = make_float2(xv, xv);
    }
#pragma unroll
    for (int i = 0; i < RR; i++) {
#pragma unroll
        for (int jt = 0; jt < JT; jt++) {
            float p = pimg[(row0 + i) * Wc + tid + jt * TPB];
            pr[i][jt] = p;
            float p2 = p * p;
            float w  = p2 * p2 + Cc;
            float iw = __fdividef(1.0f, w);
            float iw2 = iw * iw;
            iw2d[i][jt] = make_float2(iw2, iw2);
        }
    }
    __syncthreads();

    float pixmin[RR][JT];
#pragma unroll
    for (int i = 0; i < RR; i++)
#pragma unroll
        for (int jt = 0; jt < JT; jt++) pixmin[i][jt] = 3.0e38f;

    const float2* s_gx2 = (const float2*)s_gx;

#pragma unroll 2
    for (int m0 = 0; m0 < Mc; m0 += MC) {
        float2 dx2p[JT][MC / 2];
        float2 t2p[MC / 2];
#pragma unroll
        for (int mp = 0; mp < MC / 2; mp++) {
            float2 gxp = s_gx2[(m0 >> 1) + mp];          // broadcast LDS.64
            t2p[mp] = make_float2(3.0e38f, 3.0e38f);
#pragma unroll
            for (int jt = 0; jt < JT; jt++) {
                float2 dxp = f2sub(xjd[jt], gxp);
                dx2p[jt][mp] = f2mul(dxp, dxp);
            }
        }
#pragma unroll
        for (int i = 0; i < RR; i++) {
            const float2* dy2row = (const float2*)(s_dy2 + i * Mc + m0);
#pragma unroll
            for (int mp = 0; mp < MC / 2; mp++) {
                float2 dy2p = dy2row[mp];                 // broadcast LDS.64
#pragma unroll
                for (int jt = 0; jt < JT; jt++) {
                    float2 d2 = f2add(dy2p, dx2p[jt][mp]);
                    float2 t  = f2mul(d2, iw2d[i][jt]);
                    pixmin[i][jt] = fminf(pixmin[i][jt], fminf(d2.x, d2.y));
                    t2p[mp].x = fminf(t2p[mp].x, t.x);
                    t2p[mp].y = fminf(t2p[mp].y, t.y);
                }
            }
        }
        // per-thread mins -> single slot per m (single-bank ATOMS, no result dep)
#pragma unroll
        for (int mp = 0; mp < MC / 2; mp++) {
            atomicMin(&s_t2min[m0 + 2 * mp],     __float_as_int(t2p[mp].x));
            atomicMin(&s_t2min[m0 + 2 * mp + 1], __float_as_int(t2p[mp].y));
        }
    }

    // term1 partials: sum p * sqrt(min_m d2), and sum p
    float t1p = 0.0f, pp = 0.0f;
#pragma unroll
    for (int i = 0; i < RR; i++) {
#pragma unroll
        for (int jt = 0; jt < JT; jt++) {
            t1p += pr[i][jt] * sqrtf(pixmin[i][jt]);
            pp  += pr[i][jt];
        }
    }
#pragma unroll
    for (int off = 16; off >= 1; off >>= 1) {
        t1p += __shfl_xor_sync(0xffffffffu, t1p, off);
        pp  += __shfl_xor_sync(0xffffffffu, pp,  off);
    }
    if (lane == 0) { s_red[wrp] = t1p; s_red[6 + wrp] = pp; }
    __syncthreads();   // also covers s_t2min atomics
    if (tid == 0) {
        float a = 0.0f, c = 0.0f;
#pragma unroll
        for (int w = 0; w < 6; w++) { a += s_red[w]; c += s_red[6 + w]; }
        g_t1part[blk] = a;
        g_ppart[blk]  = c;
    }

    // block t2 mins -> global keys (1 m per thread)
    atomicMax(&g_t2key[b * Mc + tid], 0x7F800000 - s_t2min[tid]);

    // ---- last-block finalize ----
    __threadfence();
    __syncthreads();
    if (tid == 0) s_last = (atomicAdd(&g_ctr, 1) == NBLOCKS - 1);
    __syncthreads();
    if (!s_last) return;

    __shared__ float s_t2[Bc], s_t1s[Bc], s_pps[Bc];
    // term2: first 128 threads own 6 keys each; image = tid/32 = wrp (tid<128)
    if (tid < 128) {
        float acc = 0.0f;
#pragma unroll
        for (int k = 0; k < 6; k++) {
            int idx = tid * 6 + k;
            int key = __ldcg(&g_t2key[idx]);
            float v = __int_as_float(0x7F800000 - key);
            acc += fminf(sqrtf(v), MAXD);
            g_t2key[idx] = 0;                    // reset for next call
        }
#pragma unroll
        for (int off = 16; off >= 1; off >>= 1)
            acc += __shfl_xor_sync(0xffffffffu, acc, off);
        if (lane == 0) s_t2[wrp] = acc;          // warp w == image w
    }
    // term1: warp w (w<4) reduces the 64 block-partials of image w
    if (wrp < Bc) {
        float t1 = __ldcg(&g_t1part[wrp * TILES + lane]) +
                   __ldcg(&g_t1part[wrp * TILES + 32 + lane]);
        float ps = __ldcg(&g_ppart [wrp * TILES + lane]) +
                   __ldcg(&g_ppart [wrp * TILES + 32 + lane]);
#pragma unroll
        for (int off = 16; off >= 1; off >>= 1) {
            t1 += __shfl_xor_sync(0xffffffffu, t1, off);
            ps += __shfl_xor_sync(0xffffffffu, ps, off);
        }
        if (lane == 0) { s_t1s[wrp] = t1; s_pps[wrp] = ps; }
    }
    __syncthreads();
    if (tid == 0) {
        float res = 0.0f;
#pragma unroll
        for (int b2 = 0; b2 < Bc; b2++) {
            res += s_t1s[b2] / (s_pps[b2] + EPSc);
            res += s_t2[b2] * (1.0f / (float)Mc);
        }
        out[0] = res * (1.0f / (float)Bc);
        g_ctr = 0;                               // reset for next call
    }
}

extern "C" void kernel_launch(void* const* d_in, const int* in_sizes, int n_in,
                              void* d_out, int out_size) {
    const float* prob = (const float*)d_in[0];
    const float* gt   = (const float*)d_in[1];
    const float* osz  = (const float*)d_in[2];
    float* out = (float*)d_out;

    whd_kernel<<<NBLOCKS, TPB>>>(prob, gt, osz, out);
}

// round 11
// speedup vs baseline: 1.2274x; 1.1356x over previous
#include <cuda_runtime.h>
#include <cuda_fp16.h>
#include <math.h>

// Problem constants (match reference)
#define Hc 384
#define Wc 384
#define Bc 4
#define Mc 192
#define EPSc 1e-6f
#define MAXD 543.0580079f        // sqrt(384^2 + 384^2)
#define Cc (EPSc / MAXD)         // EPS / MAX_DIST

// Coordinate scale: distances computed at 1/4 scale so d2 (<=294849) maps to
// <=18428, comfortably inside fp16 range. True d = 4*sqrt(d2_scaled).
#define SC 0.25f

// Tiling (R10-proven shape)
#define TPB 192
#define JT 2          // columns per thread: 192*2 = 384 = W
#define RR 6          // rows per block
#define MC 8          // m-chunk (4 packed pairs)
#define TILES (Hc / RR)            // 64 row tiles per image
#define NBLOCKS (Bc * TILES)       // 256 blocks

#define HINF_BITS 0x7C00           // fp16 +inf

// Persistent scratch. Zero-init is semantically "+inf" for t2 keys
// (key = 0x7C00 - halfbits, atomicMax), 0 for the counter.
// Finisher block resets both -> deterministic graph replays.
__device__ int   g_t2key[Bc * Mc];
__device__ float g_t1part[NBLOCKS];
__device__ float g_ppart[NBLOCKS];
__device__ int   g_ctr;

__global__ __launch_bounds__(TPB) void whd_kernel(
    const float* __restrict__ prob,
    const float* __restrict__ gt,
    const float* __restrict__ osz,
    float* __restrict__ out)
{
    const int blk  = blockIdx.x;
    const int b    = blk / TILES;
    const int row0 = (blk % TILES) * RR;
    const int tid  = threadIdx.x;
    const int lane = tid & 31;
    const int wrp  = tid >> 5;

    __shared__ __align__(16) float    s_gxs[Mc];           // scaled gx
    __shared__ __align__(16) unsigned s_dy2h[RR * (Mc/2)]; // half2 dy2 pairs
    __shared__ __align__(16) int      s_t2min[Mc];         // fp16 bits per m
    __shared__ float s_red[12];
    __shared__ int s_last;

    // init t2 table to fp16 +inf (1 per thread)
    s_t2min[tid] = HINF_BITS;

    const float fys = osz[b * 2 + 0] * (SC / (float)Hc);
    const float fxs = osz[b * 2 + 1] * (SC / (float)Wc);

    const float2* gt2 = (const float2*)gt;
    // scaled gx, one m per thread
    s_gxs[tid] = gt2[b * Mc + tid].y * fxs;
    // dy2 half2 pairs: thread t<96 owns m-pair (2t, 2t+1)
    if (tid < 96) {
        float2 g0 = gt2[b * Mc + 2 * tid];
        float2 g1 = gt2[b * Mc + 2 * tid + 1];
        float gy0 = g0.x * fys, gy1 = g1.x * fys;
#pragma unroll
        for (int k = 0; k < RR; k++) {
            float yv = (float)(row0 + k) * fys;
            float d0 = yv - gy0, d1 = yv - gy1;
            __half2 h = __floats2half2_rn(d0 * d0, d1 * d1);
            s_dy2h[k * (Mc/2) + tid] = *(unsigned*)&h;
        }
    }

    // Per-pixel p and iw2 = 1/w^2 (w = p^4 + EPS/MAX_DIST), fp16 duplicated.
    // iw2 overflow -> fp16 inf: such pixels correctly lose every t2 min.
    const float* pimg = prob + b * Hc * Wc;
    float   pr[RR][JT];
    __half2 iw2h[RR][JT];
    float   xs[JT];
#pragma unroll
    for (int jt = 0; jt < JT; jt++) xs[jt] = (float)(tid + jt * TPB) * fxs;
#pragma unroll
    for (int i = 0; i < RR; i++) {
#pragma unroll
        for (int jt = 0; jt < JT; jt++) {
            float p = pimg[(row0 + i) * Wc + tid + jt * TPB];
            pr[i][jt] = p;
            float p2 = p * p;
            float w  = p2 * p2 + Cc;
            float iw = __fdividef(1.0f, w);
            iw2h[i][jt] = __half2half2(__float2half_rn(iw * iw));
        }
    }
    __syncthreads();

    const __half2 hinf2 = __halves2half2(__ushort_as_half(HINF_BITS),
                                         __ushort_as_half(HINF_BITS));
    __half2 pixacc[RR][JT];
#pragma unroll
    for (int i = 0; i < RR; i++)
#pragma unroll
        for (int jt = 0; jt < JT; jt++) pixacc[i][jt] = hinf2;

    const float2* s_gx2 = (const float2*)s_gxs;

#pragma unroll 2
    for (int m0 = 0; m0 < Mc; m0 += MC) {
        __half2 dx2h[JT][MC / 2];
        __half2 t2acc[MC / 2];
#pragma unroll
        for (int mp = 0; mp < MC / 2; mp++) {
            float2 gxp = s_gx2[(m0 >> 1) + mp];          // broadcast LDS.64
            t2acc[mp] = hinf2;
#pragma unroll
            for (int jt = 0; jt < JT; jt++) {
                float dx0 = xs[jt] - gxp.x;
                float dx1 = xs[jt] - gxp.y;
                dx2h[jt][mp] = __floats2half2_rn(dx0 * dx0, dx1 * dx1);
            }
        }
#pragma unroll
        for (int i = 0; i < RR; i++) {
            // 8 dy2 halves for this chunk in one LDS.128
            uint4 q = *(const uint4*)&s_dy2h[i * (Mc/2) + (m0 >> 1)];
            __half2 dyp[4];
            dyp[0] = *(__half2*)&q.x; dyp[1] = *(__half2*)&q.y;
            dyp[2] = *(__half2*)&q.z; dyp[3] = *(__half2*)&q.w;
#pragma unroll
            for (int mp = 0; mp < MC / 2; mp++) {
#pragma unroll
                for (int jt = 0; jt < JT; jt++) {
                    __half2 d2 = __hadd2(dyp[mp], dx2h[jt][mp]);
                    __half2 t  = __hmul2(d2, iw2h[i][jt]);
                    pixacc[i][jt] = __hmin2(pixacc[i][jt], d2);
                    t2acc[mp]     = __hmin2(t2acc[mp], t);
                }
            }
        }
        // per-thread mins -> per-m slots (monotonic fp16 bits as int)
#pragma unroll
        for (int mp = 0; mp < MC / 2; mp++) {
            unsigned v = *(unsigned*)&t2acc[mp];
            atomicMin(&s_t2min[m0 + 2 * mp],     (int)(v & 0xFFFFu));
            atomicMin(&s_t2min[m0 + 2 * mp + 1], (int)(v >> 16));
        }
    }

    // term1 partials: sum p * 4*sqrt(min_m d2_scaled), and sum p
    float t1p = 0.0f, pp = 0.0f;
#pragma unroll
    for (int i = 0; i < RR; i++) {
#pragma unroll
        for (int jt = 0; jt < JT; jt++) {
            float f0 = __low2float(pixacc[i][jt]);
            float f1 = __high2float(pixacc[i][jt]);
            float mn = fminf(f0, f1);
            t1p += pr[i][jt] * (4.0f * sqrtf(mn));
            pp  += pr[i][jt];
        }
    }
#pragma unroll
    for (int off = 16; off >= 1; off >>= 1) {
        t1p += __shfl_xor_sync(0xffffffffu, t1p, off);
        pp  += __shfl_xor_sync(0xffffffffu, pp,  off);
    }
    if (lane == 0) { s_red[wrp] = t1p; s_red[6 + wrp] = pp; }
    __syncthreads();   // also covers s_t2min atomics
    if (tid == 0) {
        float a = 0.0f, c = 0.0f;
#pragma unroll
        for (int w = 0; w < 6; w++) { a += s_red[w]; c += s_red[6 + w]; }
        g_t1part[blk] = a;
        g_ppart[blk]  = c;
    }

    // block t2 mins -> global keys (1 m per thread)
    atomicMax(&g_t2key[b * Mc + tid], HINF_BITS - s_t2min[tid]);

    // ---- last-block finalize ----
    __threadfence();
    __syncthreads();
    if (tid == 0) s_last = (atomicAdd(&g_ctr, 1) == NBLOCKS - 1);
    __syncthreads();
    if (!s_last) return;

    __shared__ float s_t2[Bc], s_t1s[Bc], s_pps[Bc];
    // term2: first 128 threads own 6 keys each; image = tid/32 = wrp (tid<128)
    if (tid < 128) {
        float acc = 0.0f;
#pragma unroll
        for (int k = 0; k < 6; k++) {
            int idx = tid * 6 + k;
            int key = __ldcg(&g_t2key[idx]);
            unsigned short hb = (unsigned short)(HINF_BITS - key);
            float v = __half2float(__ushort_as_half(hb));   // scaled t2 min
            acc += fminf(4.0f * sqrtf(v), MAXD);            // inf -> clipped
            g_t2key[idx] = 0;                               // reset
        }
#pragma unroll
        for (int off = 16; off >= 1; off >>= 1)
            acc += __shfl_xor_sync(0xffffffffu, acc, off);
        if (lane == 0) s_t2[wrp] = acc;          // warp w == image w
    }
    // term1: warp w (w<4) reduces the 64 block-partials of image w
    if (wrp < Bc) {
        float t1 = __ldcg(&g_t1part[wrp * TILES + lane]) +
                   __ldcg(&g_t1part[wrp * TILES + 32 + lane]);
        float ps = __ldcg(&g_ppart [wrp * TILES + lane]) +
                   __ldcg(&g_ppart [wrp * TILES + 32 + lane]);
#pragma unroll
        for (int off = 16; off >= 1; off >>= 1) {
            t1 += __shfl_xor_sync(0xffffffffu, t1, off);
            ps += __shfl_xor_sync(0xffffffffu, ps, off);
        }
        if (lane == 0) { s_t1s[wrp] = t1; s_pps[wrp] = ps; }
    }
    __syncthreads();
    if (tid == 0) {
        float res = 0.0f;
#pragma unroll
        for (int b2 = 0; b2 < Bc; b2++) {
            res += s_t1s[b2] / (s_pps[b2] + EPSc);
            res += s_t2[b2] * (1.0f / (float)Mc);
        }
        out[0] = res * (1.0f / (float)Bc);
        g_ctr = 0;                               // reset for next call
    }
}

extern "C" void kernel_launch(void* const* d_in, const int* in_sizes, int n_in,
                              void* d_out, int out_size) {
    const float* prob = (const float*)d_in[0];
    const float* gt   = (const float*)d_in[1];
    const float* osz  = (const float*)d_in[2];
    float* out = (float*)d_out;

    whd_kernel<<<NBLOCKS, TPB>>>(prob, gt, osz, out);
}

// round 14
// speedup vs baseline: 1.2709x; 1.0355x over previous
#include <cuda_runtime.h>
#include <cuda_fp16.h>
#include <math.h>

// Problem constants (match reference)
#define Hc 384
#define Wc 384
#define Bc 4
#define Mc 192
#define EPSc 1e-6f
#define MAXD 543.0580079f        // sqrt(384^2 + 384^2)
#define Cc (EPSc / MAXD)         // EPS / MAX_DIST

// Coordinate scale: distances computed at 1/4 scale so d2 (<=294849) maps to
// <=18428, comfortably inside fp16 range. True d = 4*sqrt(d2_scaled).
#define SC 0.25f

// Tiling (R11-proven shape)
#define TPB 192
#define JT 2          // columns per thread: 192*2 = 384 = W
#define RR 6          // rows per block
#define MC 8          // m-chunk (4 packed pairs)
#define TILES (Hc / RR)            // 64 row tiles per image
#define NBLOCKS (Bc * TILES)       // 256 blocks

#define HINF_BITS 0x7C00           // fp16 +inf

// Persistent scratch. Zero-init is semantically "+inf" for t2 keys
// (key = 0x7C00 - halfbits, atomicMax), 0 for the counter.
// Finisher block resets both -> deterministic graph replays.
__device__ int   g_t2key[Bc * Mc];
__device__ float g_t1part[NBLOCKS];
__device__ float g_ppart[NBLOCKS];
__device__ int   g_ctr;

__global__ __launch_bounds__(TPB, 2) void whd_kernel(
    const float* __restrict__ prob,
    const float* __restrict__ gt,
    const float* __restrict__ osz,
    float* __restrict__ out)
{
    const int blk  = blockIdx.x;
    const int b    = blk / TILES;
    const int row0 = (blk % TILES) * RR;
    const int tid  = threadIdx.x;
    const int lane = tid & 31;
    const int wrp  = tid >> 5;

    __shared__ __align__(16) float    s_gxs[Mc];           // scaled gx
    __shared__ __align__(16) unsigned s_dy2h[RR * (Mc/2)]; // half2 dy2 pairs
    __shared__ __align__(16) int      s_t2min[Mc];         // fp16 bits per m
    __shared__ float s_red[12];
    __shared__ int s_last;

    // init t2 table to fp16 +inf (1 per thread)
    s_t2min[tid] = HINF_BITS;

    const float fys = osz[b * 2 + 0] * (SC / (float)Hc);
    const float fxs = osz[b * 2 + 1] * (SC / (float)Wc);

    const float2* gt2 = (const float2*)gt;
    // scaled gx, one m per thread
    s_gxs[tid] = gt2[b * Mc + tid].y * fxs;
    // dy2 half2 pairs: thread t<96 owns m-pair (2t, 2t+1)
    if (tid < 96) {
        float2 g0 = gt2[b * Mc + 2 * tid];
        float2 g1 = gt2[b * Mc + 2 * tid + 1];
        float gy0 = g0.x * fys, gy1 = g1.x * fys;
#pragma unroll
        for (int k = 0; k < RR; k++) {
            float yv = (float)(row0 + k) * fys;
            float d0 = yv - gy0, d1 = yv - gy1;
            __half2 h = __floats2half2_rn(d0 * d0, d1 * d1);
            s_dy2h[k * (Mc/2) + tid] = *(unsigned*)&h;
        }
    }

    // Per-pixel p and iw2 = 1/w^2 (w = p^4 + EPS/MAX_DIST), fp16 duplicated.
    // iw2 overflow -> fp16 inf: such pixels correctly lose every t2 min.
    const float* pimg = prob + b * Hc * Wc;
    float   pr[RR][JT];
    __half2 iw2h[RR][JT];
    float   xs[JT];
#pragma unroll
    for (int jt = 0; jt < JT; jt++) xs[jt] = (float)(tid + jt * TPB) * fxs;
#pragma unroll
    for (int i = 0; i < RR; i++) {
#pragma unroll
        for (int jt = 0; jt < JT; jt++) {
            float p = pimg[(row0 + i) * Wc + tid + jt * TPB];
            pr[i][jt] = p;
            float p2 = p * p;
            float w  = p2 * p2 + Cc;
            float iw = __fdividef(1.0f, w);
            iw2h[i][jt] = __half2half2(__float2half_rn(iw * iw));
        }
    }
    __syncthreads();

    const __half2 hinf2 = __halves2half2(__ushort_as_half(HINF_BITS),
                                         __ushort_as_half(HINF_BITS));
    __half2 pixacc[RR][JT];
#pragma unroll
    for (int i = 0; i < RR; i++)
#pragma unroll
        for (int jt = 0; jt < JT; jt++) pixacc[i][jt] = hinf2;

    const float2* s_gx2 = (const float2*)s_gxs;

#pragma unroll 3
    for (int m0 = 0; m0 < Mc; m0 += MC) {
        __half2 dx2h[JT][MC / 2];
        __half2 t2acc[MC / 2];
#pragma unroll
        for (int mp = 0; mp < MC / 2; mp++) {
            float2 gxp = s_gx2[(m0 >> 1) + mp];          // broadcast LDS.64
            t2acc[mp] = hinf2;
#pragma unroll
            for (int jt = 0; jt < JT; jt++) {
                // fp32 subtract (exact-ish), fp16 square
                __half2 dxh = __floats2half2_rn(xs[jt] - gxp.x,
                                                xs[jt] - gxp.y);
                dx2h[jt][mp] = __hmul2(dxh, dxh);
            }
        }
#pragma unroll
        for (int i = 0; i < RR; i++) {
            // 8 dy2 halves for this chunk in one LDS.128
            uint4 q = *(const uint4*)&s_dy2h[i * (Mc/2) + (m0 >> 1)];
            __half2 dyp[4];
            dyp[0] = *(__half2*)&q.x; dyp[1] = *(__half2*)&q.y;
            dyp[2] = *(__half2*)&q.z; dyp[3] = *(__half2*)&q.w;
#pragma unroll
            for (int mp = 0; mp < MC / 2; mp++) {
#pragma unroll
                for (int jt = 0; jt < JT; jt++) {
                    __half2 d2 = __hadd2(dyp[mp], dx2h[jt][mp]);
                    __half2 t  = __hmul2(d2, iw2h[i][jt]);
                    pixacc[i][jt] = __hmin2(pixacc[i][jt], d2);
                    t2acc[mp]     = __hmin2(t2acc[mp], t);
                }
            }
        }
        // per-thread mins -> per-m slots (monotonic fp16 bits as int)
#pragma unroll
        for (int mp = 0; mp < MC / 2; mp++) {
            unsigned v = *(unsigned*)&t2acc[mp];
            atomicMin(&s_t2min[m0 + 2 * mp],     (int)(v & 0xFFFFu));
            atomicMin(&s_t2min[m0 + 2 * mp + 1], (int)(v >> 16));
        }
    }

    // term1 partials: sum p * 4*sqrt(min_m d2_scaled), and sum p
    float t1p = 0.0f, pp = 0.0f;
#pragma unroll
    for (int i = 0; i < RR; i++) {
#pragma unroll
        for (int jt = 0; jt < JT; jt++) {
            float f0 = __low2float(pixacc[i][jt]);
            float f1 = __high2float(pixacc[i][jt]);
            float mn = fminf(f0, f1);
            t1p += pr[i][jt] * (4.0f * sqrtf(mn));
            pp  += pr[i][jt];
        }
    }
#pragma unroll
    for (int off = 16; off >= 1; off >>= 1) {
        t1p += __shfl_xor_sync(0xffffffffu, t1p, off);
        pp  += __shfl_xor_sync(0xffffffffu, pp,  off);
    }
    if (lane == 0) { s_red[wrp] = t1p; s_red[6 + wrp] = pp; }
    __syncthreads();   // also covers s_t2min atomics
    if (tid == 0) {
        float a = 0.0f, c = 0.0f;
#pragma unroll
        for (int w = 0; w < 6; w++) { a += s_red[w]; c += s_red[6 + w]; }
        g_t1part[blk] = a;
        g_ppart[blk]  = c;
    }

    // block t2 mins -> global keys (1 m per thread)
    atomicMax(&g_t2key[b * Mc + tid], HINF_BITS - s_t2min[tid]);

    // ---- last-block finalize ----
    __threadfence();
    __syncthreads();
    if (tid == 0) s_last = (atomicAdd(&g_ctr, 1) == NBLOCKS - 1);
    __syncthreads();
    if (!s_last) return;

    __shared__ float s_t2[Bc], s_t1s[Bc], s_pps[Bc];
    // term2: first 128 threads own 6 keys each; image = tid/32 = wrp (tid<128)
    if (tid < 128) {
        float acc = 0.0f;
#pragma unroll
        for (int k = 0; k < 6; k++) {
            int idx = tid * 6 + k;
            int key = __ldcg(&g_t2key[idx]);
            unsigned short hb = (unsigned short)(HINF_BITS - key);
            float v = __half2float(__ushort_as_half(hb));   // scaled t2 min
            acc += fminf(4.0f * sqrtf(v), MAXD);            // inf -> clipped
            g_t2key[idx] = 0;                               // reset
        }
#pragma unroll
        for (int off = 16; off >= 1; off >>= 1)
            acc += __shfl_xor_sync(0xffffffffu, acc, off);
        if (lane == 0) s_t2[wrp] = acc;          // warp w == image w
    }
    // term1: warp w (w<4) reduces the 64 block-partials of image w
    if (wrp < Bc) {
        float t1 = __ldcg(&g_t1part[wrp * TILES + lane]) +
                   __ldcg(&g_t1part[wrp * TILES + 32 + lane]);
        float ps = __ldcg(&g_ppart [wrp * TILES + lane]) +
                   __ldcg(&g_ppart [wrp * TILES + 32 + lane]);
#pragma unroll
        for (int off = 16; off >= 1; off >>= 1) {
            t1 += __shfl_xor_sync(0xffffffffu, t1, off);
            ps += __shfl_xor_sync(0xffffffffu, ps, off);
        }
        if (lane == 0) { s_t1s[wrp] = t1; s_pps[wrp] = ps; }
    }
    __syncthreads();
    if (tid == 0) {
        float res = 0.0f;
#pragma unroll
        for (int b2 = 0; b2 < Bc; b2++) {
            res += s_t1s[b2] / (s_pps[b2] + EPSc);
            res += s_t2[b2] * (1.0f / (float)Mc);
        }
        out[0] = res * (1.0f / (float)Bc);
        g_ctr = 0;                               // reset for next call
    }
}

extern "C" void kernel_launch(void* const* d_in, const int* in_sizes, int n_in,
                              void* d_out, int out_size) {
    const float* prob = (const float*)d_in[0];
    const float* gt   = (const float*)d_in[1];
    const float* osz  = (const float*)d_in[2];
    float* out = (float*)d_out;

    whd_kernel<<<NBLOCKS, TPB>>>(prob, gt, osz, out);
}